// round 14
// baseline (speedup 1.0000x reference)
#include <cuda_runtime.h>
#include <cuda_bf16.h>
#include <math.h>

#define N_ROWS 4096
#define V_SIZE 50000
#define D_DIM  300
#define VSP    312    // v_s padded row stride (floats)
#define GP     320    // g_pacc row stride
#define BM     64
#define BN     64
#define SPLITS 16
#define VC     3136   // vocab rows per split; last split = 2960

typedef unsigned long long u64;

// ---------------- packed f32x2 helpers ----------------
__device__ __forceinline__ u64 pack2(float lo, float hi) {
    u64 r; asm("mov.b64 %0, {%1, %2};" : "=l"(r) : "f"(lo), "f"(hi)); return r;
}
__device__ __forceinline__ void unpack2(float& lo, float& hi, u64 v) {
    asm("mov.b64 {%0, %1}, %2;" : "=f"(lo), "=f"(hi) : "l"(v));
}
__device__ __forceinline__ u64 fma2(u64 a, u64 b, u64 c) {
    u64 d; asm("fma.rn.f32x2 %0, %1, %2, %3;" : "=l"(d) : "l"(a), "l"(b), "l"(c)); return d;
}
__device__ __forceinline__ u64 mul2(u64 a, u64 b) {
    u64 d; asm("mul.rn.f32x2 %0, %1, %2;" : "=l"(d) : "l"(a), "l"(b)); return d;
}

// ---------------- scratch ----------------
__device__ float g_wp  [N_ROWS * D_DIM];
__device__ float g_pacc[SPLITS * N_ROWS * GP];
__device__ float g_pm  [SPLITS * N_ROWS];
__device__ float g_pl  [SPLITS * N_ROWS];

// ---------------- fast exp on FFMA pipe ----------------
__device__ __forceinline__ float fexp(float x) {
    float p = x * 1.4426950408889634f;
    p = fmaxf(p, -120.0f);
    float fn = rintf(p);
    float f  = p - fn;
    float y = 1.3333558146e-3f;
    y = fmaf(y, f, 9.6181291076e-3f);
    y = fmaf(y, f, 5.5504108664e-2f);
    y = fmaf(y, f, 2.4022650695e-1f);
    y = fmaf(y, f, 6.9314718055e-1f);
    y = fmaf(y, f, 1.0f);
    int e = (int)fn;
    float s = __int_as_float((e + 127) << 23);
    return y * s;
}

// ---------------- kernel 1: wp = words @ W ----------------
__global__ __launch_bounds__(320)
void gemm1_kernel(const float* __restrict__ words, const float* __restrict__ W) {
    __shared__ float ws[16 * D_DIM];
    int i0 = blockIdx.x * 16;
    int tid = threadIdx.x;
    for (int t = tid; t < 16 * D_DIM; t += 320)
        ws[t] = words[i0 * D_DIM + t];
    __syncthreads();
    int d = tid;
    if (d < D_DIM) {
        float acc[16];
        #pragma unroll
        for (int r = 0; r < 16; ++r) acc[r] = 0.f;
        for (int k4 = 0; k4 < D_DIM / 4; ++k4) {
            int k = k4 * 4;
            float w0 = W[(k + 0) * D_DIM + d];
            float w1 = W[(k + 1) * D_DIM + d];
            float w2 = W[(k + 2) * D_DIM + d];
            float w3 = W[(k + 3) * D_DIM + d];
            #pragma unroll
            for (int r = 0; r < 16; ++r) {
                float4 wv = *(const float4*)&ws[r * D_DIM + k];
                acc[r] = fmaf(wv.x, w0, acc[r]);
                acc[r] = fmaf(wv.y, w1, acc[r]);
                acc[r] = fmaf(wv.z, w2, acc[r]);
                acc[r] = fmaf(wv.w, w3, acc[r]);
            }
        }
        #pragma unroll
        for (int r = 0; r < 16; ++r)
            g_wp[(i0 + r) * D_DIM + d] = acc[r];
    }
}

// ---------------- kernel 2: fused flash (restructured) ----------------
// smem floats:
//   wp_sT [300][64]     19200
//   v_s   [64][312]     19968
//   vT    2 x [64][66]   8448  (double-buffered K-chunk transpose)
//   p2    [64 x 65] u64  8320  (dup (p,p) pairs, [j][i], stride 65)
//   m/l/al 3*64           192
#define OFF_WP   0
#define OFF_V    (OFF_WP + 300*64)
#define OFF_VT   (OFF_V  + 64*VSP)
#define OFF_P2   (OFF_VT + 2*64*66)
#define OFF_MLA  (OFF_P2 + 64*65*2)
#define SMEM_FLOATS (OFF_MLA + 192)
#define SMEM_BYTES  (SMEM_FLOATS * 4)

__device__ __forceinline__ void stage_chunk(const float* __restrict__ v_s,
                                            float* __restrict__ vT,
                                            int kbase, int tid) {
    #pragma unroll
    for (int it = 0; it < 16; ++it) {
        int t = tid + it * 256;
        int kk = t & 63;
        int j  = t >> 6;
        int col = kbase + kk;
        vT[kk * 66 + j] = (col < VSP) ? v_s[j * VSP + col] : 0.f;
    }
}

__device__ __forceinline__ void score_chunk(const float* __restrict__ wp_sT,
                                            const float* __restrict__ vT,
                                            int kbase, int klen, int ty, int tx,
                                            u64 sc2[4][2]) {
    #pragma unroll 4
    for (int kk = 0; kk < klen; ++kk) {
        float4 a4 = *(const float4*)&wp_sT[(kbase + kk) * 64 + 4 * ty];
        u64 b0 = *(const u64*)&vT[kk * 66 + 2 * tx];
        u64 b1 = *(const u64*)&vT[kk * 66 + 2 * tx + 32];
        u64 a0 = pack2(a4.x, a4.x);
        u64 a1 = pack2(a4.y, a4.y);
        u64 a2 = pack2(a4.z, a4.z);
        u64 a3 = pack2(a4.w, a4.w);
        sc2[0][0] = fma2(a0, b0, sc2[0][0]); sc2[0][1] = fma2(a0, b1, sc2[0][1]);
        sc2[1][0] = fma2(a1, b0, sc2[1][0]); sc2[1][1] = fma2(a1, b1, sc2[1][1]);
        sc2[2][0] = fma2(a2, b0, sc2[2][0]); sc2[2][1] = fma2(a2, b1, sc2[2][1]);
        sc2[3][0] = fma2(a3, b0, sc2[3][0]); sc2[3][1] = fma2(a3, b1, sc2[3][1]);
    }
}

__global__ __launch_bounds__(256, 1)
void fused_kernel(const float* __restrict__ vocab) {
    extern __shared__ float sm[];
    float* wp_sT = sm + OFF_WP;
    float* v_s   = sm + OFF_V;
    float* vT0   = sm + OFF_VT;
    float* vT1   = vT0 + 64 * 66;
    u64*   p2    = (u64*)(sm + OFF_P2);
    float* m_s   = sm + OFF_MLA;
    float* l_s   = m_s + 64;
    float* al_s  = l_s + 64;

    const int tid    = threadIdx.x;
    const int row0   = blockIdx.x * BM;
    const int split  = blockIdx.y;
    const int jbeg   = split * VC;
    const int jend   = min(V_SIZE, jbeg + VC);
    const int ntiles = (jend - jbeg + BN - 1) / BN;

    // score mapping: 16x16 grid; rows 4ty..+3; cols {2tx,2tx+1,2tx+32,2tx+33}
    const int ty = tid >> 4;
    const int tx = tid & 15;
    // value mapping: 8 row-groups x 32 d-lanes
    const int rg = tid >> 5;
    const int dc = tid & 31;
    const bool c4ok = (dc < 28);

    // one-time wp tile load (K-major)
    for (int t = tid; t < BM * D_DIM; t += 256) {
        int i = t & 63;
        int d = t >> 6;
        wp_sT[d * 64 + i] = g_wp[(row0 + i) * D_DIM + d];
    }
    if (tid < 64) { m_s[tid] = -1e30f; l_s[tid] = 0.f; al_s[tid] = 1.f; }

    u64 o2[8][5];
    #pragma unroll
    for (int r = 0; r < 8; ++r)
        #pragma unroll
        for (int c = 0; c < 5; ++c) o2[r][c] = 0ull;

    __syncthreads();

    for (int tile = 0; tile < ntiles; ++tile) {
        const int j0    = jbeg + tile * BN;
        const int valid = min(BN, jend - j0);

        // ---- A: load vocab tile [64][312], zero-padded
        for (int t = tid; t < 64 * (VSP / 4); t += 256) {
            int j = t / (VSP / 4);
            int c = t - j * (VSP / 4);
            float4 val = make_float4(0.f, 0.f, 0.f, 0.f);
            if (j < valid && c < 75)
                val = ((const float4*)vocab)[(j0 + j) * 75 + c];
            ((float4*)v_s)[j * (VSP / 4) + c] = val;
        }
        __syncthreads();

        // ---- B: score GEMM, double-buffered staging overlapped with compute
        u64 sc2[4][2];
        #pragma unroll
        for (int r = 0; r < 4; ++r) { sc2[r][0] = 0ull; sc2[r][1] = 0ull; }

        stage_chunk(v_s, vT0, 0, tid);
        __syncthreads();
        #pragma unroll 1
        for (int ch = 0; ch < 5; ++ch) {
            const float* vTc = (ch & 1) ? vT1 : vT0;
            float*       vTn = (ch & 1) ? vT0 : vT1;
            const int klen = (ch < 4) ? 64 : (D_DIM - 256);   // 44
            score_chunk(wp_sT, vTc, ch * 64, klen, ty, tx, sc2);
            if (ch < 4) stage_chunk(v_s, vTn, (ch + 1) * 64, tid);
            __syncthreads();
        }

        // ---- C: inline online softmax (registers + shfl; no S smem)
        {
            float s[4][4];   // [r][2m+e]
            float mr[4];
            #pragma unroll
            for (int r = 0; r < 4; ++r) {
                float l0, h0, l1, h1;
                unpack2(l0, h0, sc2[r][0]);
                unpack2(l1, h1, sc2[r][1]);
                s[r][0] = l0; s[r][1] = h0; s[r][2] = l1; s[r][3] = h1;
            }
            if (valid < 64) {
                #pragma unroll
                for (int m = 0; m < 2; ++m) {
                    int jl = 2 * tx + 32 * m;
                    #pragma unroll
                    for (int r = 0; r < 4; ++r) {
                        if (jl     >= valid) s[r][2 * m]     = -1e30f;
                        if (jl + 1 >= valid) s[r][2 * m + 1] = -1e30f;
                    }
                }
            }
            #pragma unroll
            for (int r = 0; r < 4; ++r)
                mr[r] = fmaxf(fmaxf(s[r][0], s[r][1]), fmaxf(s[r][2], s[r][3]));
            #pragma unroll
            for (int off = 1; off < 16; off <<= 1)
                #pragma unroll
                for (int r = 0; r < 4; ++r)
                    mr[r] = fmaxf(mr[r], __shfl_xor_sync(0xffffffffu, mr[r], off));

            float mnew[4], alpha[4], rs[4];
            #pragma unroll
            for (int r = 0; r < 4; ++r) {
                const int i = 4 * ty + r;
                float mold = m_s[i];
                mnew[r]  = fmaxf(mold, mr[r]);
                alpha[r] = fexp(mold - mnew[r]);
                float p0 = fexp(s[r][0] - mnew[r]);
                float p1 = fexp(s[r][1] - mnew[r]);
                float p2v = fexp(s[r][2] - mnew[r]);
                float p3 = fexp(s[r][3] - mnew[r]);
                rs[r] = (p0 + p1) + (p2v + p3);
                p2[(2 * tx)      * 65 + i] = pack2(p0, p0);
                p2[(2 * tx + 1)  * 65 + i] = pack2(p1, p1);
                p2[(2 * tx + 32) * 65 + i] = pack2(p2v, p2v);
                p2[(2 * tx + 33) * 65 + i] = pack2(p3, p3);
            }
            #pragma unroll
            for (int off = 1; off < 16; off <<= 1)
                #pragma unroll
                for (int r = 0; r < 4; ++r)
                    rs[r] += __shfl_xor_sync(0xffffffffu, rs[r], off);
            if (tx == 0) {
                #pragma unroll
                for (int r = 0; r < 4; ++r) {
                    const int i = 4 * ty + r;
                    m_s[i]  = mnew[r];
                    l_s[i]  = l_s[i] * alpha[r] + rs[r];
                    al_s[i] = alpha[r];
                }
            }
        }
        __syncthreads();

        // ---- D: value GEMM accumulate (d-packed f32x2)
        {
            #pragma unroll
            for (int r = 0; r < 8; ++r) {
                float av = al_s[rg * 8 + r];
                u64 a2v = pack2(av, av);
                #pragma unroll
                for (int c = 0; c < 5; ++c) o2[r][c] = mul2(o2[r][c], a2v);
            }
            #pragma unroll 2
            for (int j = 0; j < 64; ++j) {
                const u64* pj = &p2[j * 65 + rg * 8];
                u64 pr[8];
                #pragma unroll
                for (int r = 0; r < 8; ++r) pr[r] = pj[r];
                u64 vv[5];
                #pragma unroll
                for (int c = 0; c < 4; ++c)
                    vv[c] = *(const u64*)&v_s[j * VSP + 2 * dc + 64 * c];
                vv[4] = c4ok ? *(const u64*)&v_s[j * VSP + 256 + 2 * dc] : 0ull;
                #pragma unroll
                for (int r = 0; r < 8; ++r)
                    #pragma unroll
                    for (int c = 0; c < 5; ++c)
                        o2[r][c] = fma2(pr[r], vv[c], o2[r][c]);
            }
        }
        __syncthreads();
    }

    // ---- E: write split partials
    {
        const int base = split * N_ROWS + row0;
        #pragma unroll
        for (int r = 0; r < 8; ++r) {
            float* dst = &g_pacc[(size_t)(base + rg * 8 + r) * GP];
            #pragma unroll
            for (int c = 0; c < 4; ++c)
                *(u64*)&dst[2 * dc + 64 * c] = o2[r][c];
            if (c4ok)
                *(u64*)&dst[256 + 2 * dc] = o2[r][4];
        }
        if (tid < 64) {
            g_pm[split * N_ROWS + row0 + tid] = m_s[tid];
            g_pl[split * N_ROWS + row0 + tid] = l_s[tid];
        }
    }
}

// ---------------- kernel 3: combine splits + default-embed ----------------
__global__ __launch_bounds__(320)
void combine_kernel(const float* __restrict__ words,
                    const float* __restrict__ defv,
                    float* __restrict__ out) {
    const int i   = blockIdx.x;
    const int tid = threadIdx.x;
    __shared__ float red[10];
    __shared__ float sdef_sh;

    float prod = 0.f;
    if (tid < D_DIM) prod = g_wp[i * D_DIM + tid] * defv[tid];
    #pragma unroll
    for (int off = 16; off > 0; off >>= 1)
        prod += __shfl_xor_sync(0xffffffffu, prod, off);
    if ((tid & 31) == 0) red[tid >> 5] = prod;
    __syncthreads();
    if (tid == 0) {
        float s = 0.f;
        #pragma unroll
        for (int w = 0; w < 10; ++w) s += red[w];
        sdef_sh = s;
    }
    __syncthreads();
    const float sdef = sdef_sh;

    float m[SPLITS], l[SPLITS];
    float M = sdef;
    #pragma unroll
    for (int s = 0; s < SPLITS; ++s) {
        m[s] = g_pm[s * N_ROWS + i];
        l[s] = g_pl[s * N_ROWS + i];
        M = fmaxf(M, m[s]);
    }
    float w[SPLITS];
    float edef = fexp(sdef - M);
    float L = edef;
    #pragma unroll
    for (int s = 0; s < SPLITS; ++s) {
        w[s] = fexp(m[s] - M);
        L += l[s] * w[s];
    }
    const float inv = 1.f / L;
    if (tid < D_DIM) {
        float acc = 0.f;
        #pragma unroll
        for (int s = 0; s < SPLITS; ++s)
            acc += g_pacc[(size_t)(s * N_ROWS + i) * GP + tid] * w[s];
        out[i * D_DIM + tid] = acc * inv + (edef * inv) * words[i * D_DIM + tid];
    }
}

// ---------------- launcher ----------------
extern "C" void kernel_launch(void* const* d_in, const int* in_sizes, int n_in,
                              void* d_out, int out_size) {
    const float* words = (const float*)d_in[0];   // [4096, 300]
    const float* vocab = (const float*)d_in[1];   // [50000, 300]
    const float* defv  = (const float*)d_in[2];   // [300]
    const float* W     = (const float*)d_in[3];   // [300, 300]
    float* out = (float*)d_out;                   // [4096, 300]

    cudaFuncSetAttribute(fused_kernel,
                         cudaFuncAttributeMaxDynamicSharedMemorySize, SMEM_BYTES);

    gemm1_kernel<<<N_ROWS / 16, 320>>>(words, W);
    fused_kernel<<<dim3(N_ROWS / BM, SPLITS), 256, SMEM_BYTES>>>(vocab);
    combine_kernel<<<N_ROWS, 320>>>(words, defv, out);
}

// round 15
// speedup vs baseline: 1.0032x; 1.0032x over previous
#include <cuda_runtime.h>
#include <cuda_bf16.h>
#include <math.h>

#define N_ROWS 4096
#define V_SIZE 50000
#define D_DIM  300
#define VSP    312    // v_s padded row stride (floats)
#define GP     320    // g_pacc row stride
#define BM     64
#define BN     64
#define SPLITS 16
#define VC     3136   // vocab rows per split; last split = 2960

typedef unsigned long long u64;

// ---------------- packed f32x2 helpers ----------------
__device__ __forceinline__ u64 pack2(float lo, float hi) {
    u64 r; asm("mov.b64 %0, {%1, %2};" : "=l"(r) : "f"(lo), "f"(hi)); return r;
}
__device__ __forceinline__ void unpack2(float& lo, float& hi, u64 v) {
    asm("mov.b64 {%0, %1}, %2;" : "=f"(lo), "=f"(hi) : "l"(v));
}
__device__ __forceinline__ u64 fma2(u64 a, u64 b, u64 c) {
    u64 d; asm("fma.rn.f32x2 %0, %1, %2, %3;" : "=l"(d) : "l"(a), "l"(b), "l"(c)); return d;
}
__device__ __forceinline__ u64 mul2(u64 a, u64 b) {
    u64 d; asm("mul.rn.f32x2 %0, %1, %2;" : "=l"(d) : "l"(a), "l"(b)); return d;
}

// ---------------- scratch ----------------
__device__ float g_wp  [N_ROWS * D_DIM];
__device__ float g_pacc[SPLITS * N_ROWS * GP];
__device__ float g_pm  [SPLITS * N_ROWS];
__device__ float g_pl  [SPLITS * N_ROWS];

// ---------------- fast exp on FFMA pipe ----------------
__device__ __forceinline__ float fexp(float x) {
    float p = x * 1.4426950408889634f;
    p = fmaxf(p, -120.0f);
    float fn = rintf(p);
    float f  = p - fn;
    float y = 1.3333558146e-3f;
    y = fmaf(y, f, 9.6181291076e-3f);
    y = fmaf(y, f, 5.5504108664e-2f);
    y = fmaf(y, f, 2.4022650695e-1f);
    y = fmaf(y, f, 6.9314718055e-1f);
    y = fmaf(y, f, 1.0f);
    int e = (int)fn;
    float s = __int_as_float((e + 127) << 23);
    return y * s;
}

// ---------------- kernel 1: wp = words @ W ----------------
__global__ __launch_bounds__(320)
void gemm1_kernel(const float* __restrict__ words, const float* __restrict__ W) {
    __shared__ float ws[16 * D_DIM];
    int i0 = blockIdx.x * 16;
    int tid = threadIdx.x;
    for (int t = tid; t < 16 * D_DIM; t += 320)
        ws[t] = words[i0 * D_DIM + t];
    __syncthreads();
    int d = tid;
    if (d < D_DIM) {
        float acc[16];
        #pragma unroll
        for (int r = 0; r < 16; ++r) acc[r] = 0.f;
        for (int k4 = 0; k4 < D_DIM / 4; ++k4) {
            int k = k4 * 4;
            float w0 = W[(k + 0) * D_DIM + d];
            float w1 = W[(k + 1) * D_DIM + d];
            float w2 = W[(k + 2) * D_DIM + d];
            float w3 = W[(k + 3) * D_DIM + d];
            #pragma unroll
            for (int r = 0; r < 16; ++r) {
                float4 wv = *(const float4*)&ws[r * D_DIM + k];
                acc[r] = fmaf(wv.x, w0, acc[r]);
                acc[r] = fmaf(wv.y, w1, acc[r]);
                acc[r] = fmaf(wv.z, w2, acc[r]);
                acc[r] = fmaf(wv.w, w3, acc[r]);
            }
        }
        #pragma unroll
        for (int r = 0; r < 16; ++r)
            g_wp[(i0 + r) * D_DIM + d] = acc[r];
    }
}

// ---------------- kernel 2: fused flash (restructured) ----------------
// smem floats:
//   wp_sT [300][64]     19200
//   v_s   [64][312]     19968
//   vT    2 x [64][66]   8448  (double-buffered K-chunk transpose)
//   p2    [64 x 65] u64  8320  (dup (p,p) pairs, [j][i], stride 65)
//   m/l/al 3*64           192
#define OFF_WP   0
#define OFF_V    (OFF_WP + 300*64)
#define OFF_VT   (OFF_V  + 64*VSP)
#define OFF_P2   (OFF_VT + 2*64*66)
#define OFF_MLA  (OFF_P2 + 64*65*2)
#define SMEM_FLOATS (OFF_MLA + 192)
#define SMEM_BYTES  (SMEM_FLOATS * 4)

__device__ __forceinline__ void stage_chunk(const float* __restrict__ v_s,
                                            float* __restrict__ vT,
                                            int kbase, int tid) {
    #pragma unroll
    for (int it = 0; it < 16; ++it) {
        int t = tid + it * 256;
        int kk = t & 63;
        int j  = t >> 6;
        int col = kbase + kk;
        vT[kk * 66 + j] = (col < VSP) ? v_s[j * VSP + col] : 0.f;
    }
}

__device__ __forceinline__ void score_chunk(const float* __restrict__ wp_sT,
                                            const float* __restrict__ vT,
                                            int kbase, int klen, int ty, int tx,
                                            u64 sc2[4][2]) {
    #pragma unroll 4
    for (int kk = 0; kk < klen; ++kk) {
        float4 a4 = *(const float4*)&wp_sT[(kbase + kk) * 64 + 4 * ty];
        u64 b0 = *(const u64*)&vT[kk * 66 + 2 * tx];
        u64 b1 = *(const u64*)&vT[kk * 66 + 2 * tx + 32];
        u64 a0 = pack2(a4.x, a4.x);
        u64 a1 = pack2(a4.y, a4.y);
        u64 a2 = pack2(a4.z, a4.z);
        u64 a3 = pack2(a4.w, a4.w);
        sc2[0][0] = fma2(a0, b0, sc2[0][0]); sc2[0][1] = fma2(a0, b1, sc2[0][1]);
        sc2[1][0] = fma2(a1, b0, sc2[1][0]); sc2[1][1] = fma2(a1, b1, sc2[1][1]);
        sc2[2][0] = fma2(a2, b0, sc2[2][0]); sc2[2][1] = fma2(a2, b1, sc2[2][1]);
        sc2[3][0] = fma2(a3, b0, sc2[3][0]); sc2[3][1] = fma2(a3, b1, sc2[3][1]);
    }
}

__global__ __launch_bounds__(256, 1)
void fused_kernel(const float* __restrict__ vocab) {
    extern __shared__ float sm[];
    float* wp_sT = sm + OFF_WP;
    float* v_s   = sm + OFF_V;
    float* vT0   = sm + OFF_VT;
    float* vT1   = vT0 + 64 * 66;
    u64*   p2    = (u64*)(sm + OFF_P2);
    float* m_s   = sm + OFF_MLA;
    float* l_s   = m_s + 64;
    float* al_s  = l_s + 64;

    const int tid    = threadIdx.x;
    const int row0   = blockIdx.x * BM;
    const int split  = blockIdx.y;
    const int jbeg   = split * VC;
    const int jend   = min(V_SIZE, jbeg + VC);
    const int ntiles = (jend - jbeg + BN - 1) / BN;

    // score mapping: 16x16 grid; rows 4ty..+3; cols {2tx,2tx+1,2tx+32,2tx+33}
    const int ty = tid >> 4;
    const int tx = tid & 15;
    // value mapping: 8 row-groups x 32 d-lanes
    const int rg = tid >> 5;
    const int dc = tid & 31;
    const bool c4ok = (dc < 28);

    // one-time wp tile load (K-major)
    for (int t = tid; t < BM * D_DIM; t += 256) {
        int i = t & 63;
        int d = t >> 6;
        wp_sT[d * 64 + i] = g_wp[(row0 + i) * D_DIM + d];
    }
    if (tid < 64) { m_s[tid] = -1e30f; l_s[tid] = 0.f; al_s[tid] = 1.f; }

    u64 o2[8][5];
    #pragma unroll
    for (int r = 0; r < 8; ++r)
        #pragma unroll
        for (int c = 0; c < 5; ++c) o2[r][c] = 0ull;

    __syncthreads();

    for (int tile = 0; tile < ntiles; ++tile) {
        const int j0    = jbeg + tile * BN;
        const int valid = min(BN, jend - j0);

        // ---- A: load vocab tile [64][312], zero-padded
        for (int t = tid; t < 64 * (VSP / 4); t += 256) {
            int j = t / (VSP / 4);
            int c = t - j * (VSP / 4);
            float4 val = make_float4(0.f, 0.f, 0.f, 0.f);
            if (j < valid && c < 75)
                val = ((const float4*)vocab)[(j0 + j) * 75 + c];
            ((float4*)v_s)[j * (VSP / 4) + c] = val;
        }
        __syncthreads();

        // ---- B: score GEMM, double-buffered staging overlapped with compute
        u64 sc2[4][2];
        #pragma unroll
        for (int r = 0; r < 4; ++r) { sc2[r][0] = 0ull; sc2[r][1] = 0ull; }

        stage_chunk(v_s, vT0, 0, tid);
        __syncthreads();
        #pragma unroll 1
        for (int ch = 0; ch < 5; ++ch) {
            const float* vTc = (ch & 1) ? vT1 : vT0;
            float*       vTn = (ch & 1) ? vT0 : vT1;
            const int klen = (ch < 4) ? 64 : (D_DIM - 256);   // 44
            score_chunk(wp_sT, vTc, ch * 64, klen, ty, tx, sc2);
            if (ch < 4) stage_chunk(v_s, vTn, (ch + 1) * 64, tid);
            __syncthreads();
        }

        // ---- C: inline online softmax (registers + shfl; no S smem)
        {
            float s[4][4];   // [r][2m+e]
            float mr[4];
            #pragma unroll
            for (int r = 0; r < 4; ++r) {
                float l0, h0, l1, h1;
                unpack2(l0, h0, sc2[r][0]);
                unpack2(l1, h1, sc2[r][1]);
                s[r][0] = l0; s[r][1] = h0; s[r][2] = l1; s[r][3] = h1;
            }
            if (valid < 64) {
                #pragma unroll
                for (int m = 0; m < 2; ++m) {
                    int jl = 2 * tx + 32 * m;
                    #pragma unroll
                    for (int r = 0; r < 4; ++r) {
                        if (jl     >= valid) s[r][2 * m]     = -1e30f;
                        if (jl + 1 >= valid) s[r][2 * m + 1] = -1e30f;
                    }
                }
            }
            #pragma unroll
            for (int r = 0; r < 4; ++r)
                mr[r] = fmaxf(fmaxf(s[r][0], s[r][1]), fmaxf(s[r][2], s[r][3]));
            #pragma unroll
            for (int off = 1; off < 16; off <<= 1)
                #pragma unroll
                for (int r = 0; r < 4; ++r)
                    mr[r] = fmaxf(mr[r], __shfl_xor_sync(0xffffffffu, mr[r], off));

            float mnew[4], alpha[4], rs[4];
            #pragma unroll
            for (int r = 0; r < 4; ++r) {
                const int i = 4 * ty + r;
                float mold = m_s[i];
                mnew[r]  = fmaxf(mold, mr[r]);
                alpha[r] = fexp(mold - mnew[r]);
                float p0 = fexp(s[r][0] - mnew[r]);
                float p1 = fexp(s[r][1] - mnew[r]);
                float p2v = fexp(s[r][2] - mnew[r]);
                float p3 = fexp(s[r][3] - mnew[r]);
                rs[r] = (p0 + p1) + (p2v + p3);
                p2[(2 * tx)      * 65 + i] = pack2(p0, p0);
                p2[(2 * tx + 1)  * 65 + i] = pack2(p1, p1);
                p2[(2 * tx + 32) * 65 + i] = pack2(p2v, p2v);
                p2[(2 * tx + 33) * 65 + i] = pack2(p3, p3);
            }
            #pragma unroll
            for (int off = 1; off < 16; off <<= 1)
                #pragma unroll
                for (int r = 0; r < 4; ++r)
                    rs[r] += __shfl_xor_sync(0xffffffffu, rs[r], off);
            if (tx == 0) {
                #pragma unroll
                for (int r = 0; r < 4; ++r) {
                    const int i = 4 * ty + r;
                    m_s[i]  = mnew[r];
                    l_s[i]  = l_s[i] * alpha[r] + rs[r];
                    al_s[i] = alpha[r];
                }
            }
        }
        __syncthreads();

        // ---- D: value GEMM accumulate (d-packed f32x2)
        {
            #pragma unroll
            for (int r = 0; r < 8; ++r) {
                float av = al_s[rg * 8 + r];
                u64 a2v = pack2(av, av);
                #pragma unroll
                for (int c = 0; c < 5; ++c) o2[r][c] = mul2(o2[r][c], a2v);
            }
            #pragma unroll 2
            for (int j = 0; j < 64; ++j) {
                const u64* pj = &p2[j * 65 + rg * 8];
                u64 pr[8];
                #pragma unroll
                for (int r = 0; r < 8; ++r) pr[r] = pj[r];
                u64 vv[5];
                #pragma unroll
                for (int c = 0; c < 4; ++c)
                    vv[c] = *(const u64*)&v_s[j * VSP + 2 * dc + 64 * c];
                vv[4] = c4ok ? *(const u64*)&v_s[j * VSP + 256 + 2 * dc] : 0ull;
                #pragma unroll
                for (int r = 0; r < 8; ++r)
                    #pragma unroll
                    for (int c = 0; c < 5; ++c)
                        o2[r][c] = fma2(pr[r], vv[c], o2[r][c]);
            }
        }
        __syncthreads();
    }

    // ---- E: write split partials
    {
        const int base = split * N_ROWS + row0;
        #pragma unroll
        for (int r = 0; r < 8; ++r) {
            float* dst = &g_pacc[(size_t)(base + rg * 8 + r) * GP];
            #pragma unroll
            for (int c = 0; c < 4; ++c)
                *(u64*)&dst[2 * dc + 64 * c] = o2[r][c];
            if (c4ok)
                *(u64*)&dst[256 + 2 * dc] = o2[r][4];
        }
        if (tid < 64) {
            g_pm[split * N_ROWS + row0 + tid] = m_s[tid];
            g_pl[split * N_ROWS + row0 + tid] = l_s[tid];
        }
    }
}

// ---------------- kernel 3: combine splits + default-embed ----------------
__global__ __launch_bounds__(320)
void combine_kernel(const float* __restrict__ words,
                    const float* __restrict__ defv,
                    float* __restrict__ out) {
    const int i   = blockIdx.x;
    const int tid = threadIdx.x;
    __shared__ float red[10];
    __shared__ float sdef_sh;

    float prod = 0.f;
    if (tid < D_DIM) prod = g_wp[i * D_DIM + tid] * defv[tid];
    #pragma unroll
    for (int off = 16; off > 0; off >>= 1)
        prod += __shfl_xor_sync(0xffffffffu, prod, off);
    if ((tid & 31) == 0) red[tid >> 5] = prod;
    __syncthreads();
    if (tid == 0) {
        float s = 0.f;
        #pragma unroll
        for (int w = 0; w < 10; ++w) s += red[w];
        sdef_sh = s;
    }
    __syncthreads();
    const float sdef = sdef_sh;

    float m[SPLITS], l[SPLITS];
    float M = sdef;
    #pragma unroll
    for (int s = 0; s < SPLITS; ++s) {
        m[s] = g_pm[s * N_ROWS + i];
        l[s] = g_pl[s * N_ROWS + i];
        M = fmaxf(M, m[s]);
    }
    float w[SPLITS];
    float edef = fexp(sdef - M);
    float L = edef;
    #pragma unroll
    for (int s = 0; s < SPLITS; ++s) {
        w[s] = fexp(m[s] - M);
        L += l[s] * w[s];
    }
    const float inv = 1.f / L;
    if (tid < D_DIM) {
        float acc = 0.f;
        #pragma unroll
        for (int s = 0; s < SPLITS; ++s)
            acc += g_pacc[(size_t)(s * N_ROWS + i) * GP + tid] * w[s];
        out[i * D_DIM + tid] = acc * inv + (edef * inv) * words[i * D_DIM + tid];
    }
}

// ---------------- launcher ----------------
extern "C" void kernel_launch(void* const* d_in, const int* in_sizes, int n_in,
                              void* d_out, int out_size) {
    const float* words = (const float*)d_in[0];   // [4096, 300]
    const float* vocab = (const float*)d_in[1];   // [50000, 300]
    const float* defv  = (const float*)d_in[2];   // [300]
    const float* W     = (const float*)d_in[3];   // [300, 300]
    float* out = (float*)d_out;                   // [4096, 300]

    cudaFuncSetAttribute(fused_kernel,
                         cudaFuncAttributeMaxDynamicSharedMemorySize, SMEM_BYTES);

    gemm1_kernel<<<N_ROWS / 16, 320>>>(words, W);
    fused_kernel<<<dim3(N_ROWS / BM, SPLITS), 256, SMEM_BYTES>>>(vocab);
    combine_kernel<<<N_ROWS, 320>>>(words, defv, out);
}